// round 1
// baseline (speedup 1.0000x reference)
#include <cuda_runtime.h>
#include <math.h>

#define B_DIM 64
#define S_DIM 1000
#define K_DIM 12
#define N_DIM 80
#define NP 81              // padded row stride for prep smem (odd -> conflict-free columns)
#define XPAD 251           // padded row stride for x^T staging (odd, >= 250 rows)
#define EPS 1e-5f
#define LOG_2PI 1.8378770664093453f

// Scratch (device globals: no allocation allowed in kernel_launch)
__device__ float g_W[B_DIM * K_DIM * N_DIM * N_DIM];   // W[i][j] = (L^{-T})[i][j], upper-tri, i-major
__device__ float g_c[B_DIM * K_DIM * N_DIM];           // c_j = sum_i mu_i W[i][j]
__device__ float g_cst[B_DIM * K_DIM];                 // -logdet_half - 0.5*N*log(2*pi)

typedef unsigned long long ull;

#define PACK2(d, lo, hi)   asm("mov.b64 %0, {%1, %2};" : "=l"(d) : "f"(lo), "f"(hi))
#define UNPACK2(lo, hi, s) asm("mov.b64 {%0, %1}, %2;" : "=f"(lo), "=f"(hi) : "l"(s))
#define FMA2(d, a, b, c)   asm("fma.rn.f32x2 %0, %1, %2, %3;" : "=l"(d) : "l"(a), "l"(b), "l"(c))
#define ADD2(d, a, b)      asm("add.rn.f32x2 %0, %1, %2;" : "=l"(d) : "l"(a), "l"(b))

// ---------------------------------------------------------------------------
// Prep: per (b,k): Cholesky(sigma + eps*I) -> L; M = L^{-1}; W = M^T; c = mu@W;
// cst = -sum(log diag L) - 0.5*N*log(2pi).
// One block of 128 threads per (b,k). All in shared memory.
// M[i][j] (i>j) is stored in the strict UPPER part of A at A[j*NP+i]
// (L occupies lower+diag); M diag kept in Mdiag[].
// ---------------------------------------------------------------------------
__global__ void __launch_bounds__(128) prep_kernel(const float* __restrict__ mu,
                                                   const float* __restrict__ sigma) {
    __shared__ float A[N_DIM * NP];
    __shared__ float Mdiag[N_DIM];
    int bk = blockIdx.x;
    int tid = threadIdx.x;

    const float* sig = sigma + (size_t)bk * N_DIM * N_DIM;
    for (int p = tid; p < N_DIM * N_DIM; p += 128) {
        int i = p / N_DIM, j = p % N_DIM;
        float v = sig[p];
        if (i == j) v += EPS;
        A[i * NP + j] = v;
    }
    __syncthreads();

    // Right-looking Cholesky (lower)
    for (int j = 0; j < N_DIM; j++) {
        if (tid == 0) A[j * NP + j] = sqrtf(A[j * NP + j]);
        __syncthreads();
        float d = A[j * NP + j];
        int i = j + 1 + tid;
        if (i < N_DIM) A[i * NP + j] /= d;
        __syncthreads();
        int r = j + 1 + tid;
        if (r < N_DIM) {
            float lr = A[r * NP + j];
            for (int c = j + 1; c <= r; c++) A[r * NP + c] -= lr * A[c * NP + j];
        }
        __syncthreads();
    }

    if (tid == 0) {
        float ld = 0.f;
        for (int j = 0; j < N_DIM; j++) ld += logf(A[j * NP + j]);
        g_cst[bk] = -ld - 0.5f * N_DIM * LOG_2PI;
    }

    // M = L^{-1} (forward substitution, one column per thread; no cross-thread deps:
    // thread j writes only row-j upper slots + Mdiag[j], reads L (lower+diag, frozen)
    // and its own previous writes)
    if (tid < N_DIM) {
        int j = tid;
        Mdiag[j] = 1.0f / A[j * NP + j];
        for (int i = j + 1; i < N_DIM; i++) {
            float s = 0.f;
            for (int t = j; t < i; t++) {
                float mt = (t == j) ? Mdiag[j] : A[j * NP + t];
                s -= A[i * NP + t] * mt;
            }
            A[j * NP + i] = s / A[i * NP + i];
        }
    }
    __syncthreads();

    // c_j = sum_{i<=j} mu_i * M[j][i] ;  M[j][i] (i<j) lives at A[i*NP+j]
    const float* mub = mu + (size_t)bk * N_DIM;
    if (tid < N_DIM) {
        int j = tid;
        float c = 0.f;
        for (int i = 0; i < j; i++) c += mub[i] * A[i * NP + j];
        c += mub[j] * Mdiag[j];
        g_c[bk * N_DIM + j] = c;
    }

    // W[i][j] = M[j][i]: i<j -> A[i*NP+j]; i==j -> Mdiag[i]; i>j -> 0
    float* wout = g_W + (size_t)bk * N_DIM * N_DIM;
    for (int p = tid; p < N_DIM * N_DIM; p += 128) {
        int i = p / N_DIM, j = p % N_DIM;
        float w = 0.f;
        if (i < j)      w = A[i * NP + j];
        else if (i == j) w = Mdiag[i];
        wout[p] = w;
    }
}

// ---------------------------------------------------------------------------
// Main: out[b][s][k] = -0.5*||x_s @ W_k - c_k||^2 + cst_k
// Block = (b, s-tile of 250 rows), 128 threads, thread t owns rows {t, t+125}.
// x staged transposed in smem (xs[i][r], stride 251 -> conflict-free scalar LDS);
// W_k staged in smem, read as broadcast LDS.128 -> ulonglong2 -> f32x2 FMA pairs.
// Triangular: y_j only needs i <= j; process j in 5 groups of 16, i up to 16(g+1).
// ---------------------------------------------------------------------------
__global__ void __launch_bounds__(128) ll_kernel(const float* __restrict__ x,
                                                 float* __restrict__ out) {
    extern __shared__ float sm[];
    float* xs  = sm;                       // N_DIM * XPAD
    float* Ws  = sm + N_DIM * XPAD;        // 6400
    float* csh = Ws + N_DIM * N_DIM;       // 80 (holds -c)
    float* cst_sh = csh + N_DIM;           // 1

    int b    = blockIdx.x;
    int tile = blockIdx.y;
    int tid  = threadIdx.x;
    int s0   = tile * 250;

    // Stage x^T: coalesced global reads, odd-stride smem writes (conflict-free)
    const float* xb = x + ((size_t)b * S_DIM + s0) * N_DIM;
    for (int p = tid; p < 250 * N_DIM; p += 128) {
        int r = p / N_DIM, i = p % N_DIM;
        xs[i * XPAD + r] = xb[p];
    }

    bool active = (tid < 125);

    for (int k = 0; k < K_DIM; k++) {
        __syncthreads();   // previous-k compute (and first-time x staging) done before W overwrite
        int bk = b * K_DIM + k;
        const float4* wg = (const float4*)(g_W + (size_t)bk * (N_DIM * N_DIM));
        float4* wd = (float4*)Ws;
        for (int p = tid; p < (N_DIM * N_DIM) / 4; p += 128) wd[p] = wg[p];
        for (int p = tid; p < N_DIM; p += 128) csh[p] = -g_c[bk * N_DIM + p];
        if (tid == 0) *cst_sh = g_cst[bk];
        __syncthreads();

        if (active) {
            ull accp0 = 0ULL, accp1 = 0ULL;
            #pragma unroll 1
            for (int g = 0; g < 5; g++) {
                int j0 = g * 16;
                ull y0[8], y1[8];
                #pragma unroll
                for (int q = 0; q < 8; q++) { y0[q] = 0ULL; y1[q] = 0ULL; }
                int ibound = j0 + 16;   // triangular: i <= max j in this group
                #pragma unroll 1
                for (int i = 0; i < ibound; i += 4) {
                    #pragma unroll
                    for (int u = 0; u < 4; u++) {
                        const float* xcol = xs + (i + u) * XPAD + tid;
                        float xa = xcol[0];
                        float xc = xcol[125];
                        ull xap, xbp;
                        PACK2(xap, xa, xa);
                        PACK2(xbp, xc, xc);
                        const ulonglong2* wp =
                            (const ulonglong2*)(Ws + (i + u) * N_DIM + j0);
                        #pragma unroll
                        for (int q2 = 0; q2 < 4; q2++) {
                            ulonglong2 w2 = wp[q2];   // broadcast LDS.128: 4 W floats
                            FMA2(y0[2 * q2],     xap, w2.x, y0[2 * q2]);
                            FMA2(y0[2 * q2 + 1], xap, w2.y, y0[2 * q2 + 1]);
                            FMA2(y1[2 * q2],     xbp, w2.x, y1[2 * q2]);
                            FMA2(y1[2 * q2 + 1], xbp, w2.y, y1[2 * q2 + 1]);
                        }
                    }
                }
                // epilogue: (y - c)^2 accumulated as pairs; csh holds -c
                const ull* ncp = (const ull*)(csh + j0);
                #pragma unroll
                for (int q = 0; q < 8; q++) {
                    ull nc = ncp[q];
                    ull d0, d1;
                    ADD2(d0, y0[q], nc);
                    FMA2(accp0, d0, d0, accp0);
                    ADD2(d1, y1[q], nc);
                    FMA2(accp1, d1, d1, accp1);
                }
            }
            float a0, a1, b0, b1;
            UNPACK2(a0, a1, accp0);
            UNPACK2(b0, b1, accp1);
            float cst = *cst_sh;
            size_t base = ((size_t)b * S_DIM + s0 + tid) * K_DIM + k;
            out[base]                        = fmaf(-0.5f, a0 + a1, cst);
            out[base + (size_t)125 * K_DIM]  = fmaf(-0.5f, b0 + b1, cst);
        }
    }
}

// ---------------------------------------------------------------------------
extern "C" void kernel_launch(void* const* d_in, const int* in_sizes, int n_in,
                              void* d_out, int out_size) {
    const float* x     = (const float*)d_in[0];
    const float* mu    = (const float*)d_in[1];
    const float* sigma = (const float*)d_in[2];
    float* out = (float*)d_out;

    prep_kernel<<<B_DIM * K_DIM, 128>>>(mu, sigma);

    int smem = (N_DIM * XPAD + N_DIM * N_DIM + N_DIM + 4) * (int)sizeof(float);
    cudaFuncSetAttribute(ll_kernel, cudaFuncAttributeMaxDynamicSharedMemorySize, smem);
    ll_kernel<<<dim3(B_DIM, 4), 128, smem>>>(x, out);
}